// round 13
// baseline (speedup 1.0000x reference)
#include <cuda_runtime.h>
#include <cuda_fp16.h>
#include <cstdint>

#define N_VOX    100000
#define NK       27
#define LN_EPS   1e-5f
#define NTHREADS 128
#define GRID_M   ((N_VOX + 127) / 128)   // 782

#define ROWB     144                     // A row stride bytes (72 halves)
#define STAGE_A  18432                   // 128 * 144
#define SMEM_BYTES (3 * STAGE_A)         // 55296 -> occ 4

__device__ __align__(16) __half    g_f16[N_VOX * 64];
// B fragments: [tap][nt][lane][8 regs]; reg r = k4*2+bsel,
// value = half2(W[k][n], W[k+1][n]) with n = nt*8+group, k = k4*16+qp*2+bsel*8
__device__ __align__(16) uint32_t  g_wfB[28 * 8 * 32 * 8];

// ---------- helpers ----------
__device__ __forceinline__ uint32_t smem_u32(const void* p) {
    uint32_t a;
    asm("{ .reg .u64 t; cvta.to.shared.u64 t, %1; cvt.u32.u64 %0, t; }" : "=r"(a) : "l"(p));
    return a;
}
__device__ __forceinline__ void cpa16(uint32_t dst, const void* src) {
    asm volatile("cp.async.cg.shared.global [%0], [%1], 16;" :: "r"(dst), "l"(src));
}
#define CP_COMMIT()  asm volatile("cp.async.commit_group;" ::: "memory")
#define CP_WAIT(n)   asm volatile("cp.async.wait_group %0;" :: "n"(n) : "memory")

__device__ __forceinline__ void ldsm4(uint32_t* r, uint32_t addr) {
    asm volatile("ldmatrix.sync.aligned.m8n8.x4.shared.b16 {%0,%1,%2,%3}, [%4];"
                 : "=r"(r[0]), "=r"(r[1]), "=r"(r[2]), "=r"(r[3]) : "r"(addr));
}
__device__ __forceinline__ void mma16816(float* c, const uint32_t* a,
                                         uint32_t b0, uint32_t b1) {
    asm volatile(
        "mma.sync.aligned.m16n8k16.row.col.f32.f16.f16.f32 "
        "{%0,%1,%2,%3}, {%4,%5,%6,%7}, {%8,%9}, {%0,%1,%2,%3};"
        : "+f"(c[0]), "+f"(c[1]), "+f"(c[2]), "+f"(c[3])
        : "r"(a[0]), "r"(a[1]), "r"(a[2]), "r"(a[3]), "r"(b0), "r"(b1));
}

// ---------- pre-kernels ----------
__global__ void prep_feats(const float* __restrict__ feats) {
    int t = blockIdx.x * blockDim.x + threadIdx.x;       // 8 floats / thread
    if (t >= N_VOX * 8) return;
    const float4* F = (const float4*)feats;
    float4 f0 = F[t * 2], f1 = F[t * 2 + 1];
    __half2 h0 = __floats2half2_rn(f0.x, f0.y);
    __half2 h1 = __floats2half2_rn(f0.z, f0.w);
    __half2 h2 = __floats2half2_rn(f1.x, f1.y);
    __half2 h3 = __floats2half2_rn(f1.z, f1.w);
    uint4 o;
    o.x = *(uint32_t*)&h0; o.y = *(uint32_t*)&h1;
    o.z = *(uint32_t*)&h2; o.w = *(uint32_t*)&h3;
    ((uint4*)g_f16)[t] = o;
}
__global__ void prep_wfB(const float* __restrict__ Wc, const float* __restrict__ Wl) {
    int e = blockIdx.x * blockDim.x + threadIdx.x;       // 28*2048
    if (e >= 28 * 2048) return;
    int r    = e & 7;
    int lane = (e >> 3) & 31;
    int nt   = (e >> 8) & 7;
    int tap  = e >> 11;
    int group = lane >> 2, qp = lane & 3;
    int k4 = r >> 1, bsel = r & 1;
    int n = nt * 8 + group;
    int k = k4 * 16 + qp * 2 + bsel * 8;
    float w0, w1;
    if (tap < 27) { w0 = Wc[tap * 4096 + k * 64 + n]; w1 = Wc[tap * 4096 + (k + 1) * 64 + n]; }
    else          { w0 = Wl[k * 64 + n];              w1 = Wl[(k + 1) * 64 + n]; }
    __half2 p = __floats2half2_rn(w0, w1);
    g_wfB[e] = *(uint32_t*)&p;
}

// ---------- main ----------
__global__ __launch_bounds__(NTHREADS, 4)
void conv_mma_kernel(const int* __restrict__ nb, const float* __restrict__ bc,
                     const float* __restrict__ bl, const float* __restrict__ gamma,
                     const float* __restrict__ beta, float* __restrict__ out)
{
    extern __shared__ __align__(16) char smem[];
    const uint32_t sb = smem_u32(smem);
    const int tid   = threadIdx.x;
    const int lane  = tid & 31;
    const int w     = tid >> 5;
    const int group = lane >> 2;
    const int qp    = lane & 3;
    const int gvox  = blockIdx.x * NTHREADS + tid;
    const bool active = gvox < N_VOX;
    const int* nrow = nb + (long)gvox * NK;

    float c[2][8][4];
    #pragma unroll
    for (int mi = 0; mi < 2; mi++)
        #pragma unroll
        for (int nt = 0; nt < 8; nt++)
            #pragma unroll
            for (int r = 0; r < 4; r++) c[mi][nt][r] = 0.f;

    auto issueA = [&](int s, int k) {
        uint32_t dst = sb + s * STAGE_A + tid * ROWB;
        int idx = active ? nrow[k] : -1;
        if (idx >= 0) {
            const char* src = (const char*)(g_f16 + (size_t)idx * 64);
            #pragma unroll
            for (int j = 0; j < 8; j++) cpa16(dst + j * 16, src + j * 16);
        } else {
            uint4 z = make_uint4(0, 0, 0, 0);
            char* d = smem + s * STAGE_A + tid * ROWB;
            #pragma unroll
            for (int j = 0; j < 8; j++) *(uint4*)(d + j * 16) = z;
        }
    };

    // ldmatrix base: lanes 0-15 -> rows, lanes 16-31 -> +16B (k+8)
    const uint32_t lm_base = sb + (w * 32 + (lane & 15)) * ROWB + (lane >> 4) * 16;

    auto do_tap = [&](int s, int tap) {
        uint32_t a[2][4][4];
        #pragma unroll
        for (int mi = 0; mi < 2; mi++)
            #pragma unroll
            for (int k4 = 0; k4 < 4; k4++)
                ldsm4(a[mi][k4], lm_base + s * STAGE_A + mi * 16 * ROWB + k4 * 32);
        const uint4* wf = (const uint4*)(g_wfB + (((size_t)tap * 8) * 32 + lane) * 8);
        #pragma unroll
        for (int nt = 0; nt < 8; nt++) {
            uint4 b01 = wf[nt * 64];        // regs k4=0,1
            uint4 b23 = wf[nt * 64 + 1];    // regs k4=2,3
            mma16816(c[0][nt], a[0][0], b01.x, b01.y);
            mma16816(c[1][nt], a[1][0], b01.x, b01.y);
            mma16816(c[0][nt], a[0][1], b01.z, b01.w);
            mma16816(c[1][nt], a[1][1], b01.z, b01.w);
            mma16816(c[0][nt], a[0][2], b23.x, b23.y);
            mma16816(c[1][nt], a[1][2], b23.x, b23.y);
            mma16816(c[0][nt], a[0][3], b23.z, b23.w);
            mma16816(c[1][nt], a[1][3], b23.z, b23.w);
        }
    };

    // ---- prologue: taps 0,1 ----
    issueA(0, 0); CP_COMMIT();
    issueA(1, 1); CP_COMMIT();

    // ---- conv mainloop: ONE syncthreads per tap, 3-stage ----
    #pragma unroll 1
    for (int k = 0; k < NK; k++) {
        const int s = k % 3;
        if (k < NK - 1) CP_WAIT(1); else CP_WAIT(0);
        __syncthreads();                       // tap k data visible; iter k-1 reads done
        if (k + 2 < NK) { issueA((k + 2) % 3, k + 2); CP_COMMIT(); }
        do_tap(s, k);
    }

    // ---- epilogue: +bc, fp16 X into stage0 (stage0 last read at tap 24) ----
    #pragma unroll
    for (int nt = 0; nt < 8; nt++) {
        const int col = nt * 8 + qp * 2;
        const float b0 = bc[col], b1 = bc[col + 1];
        #pragma unroll
        for (int mi = 0; mi < 2; mi++) {
            const int r0 = w * 32 + mi * 16 + group;
            float x0 = c[mi][nt][0] + b0;
            float x1 = c[mi][nt][1] + b1;
            float x2 = c[mi][nt][2] + b0;
            float x3 = c[mi][nt][3] + b1;
            __half2 p0 = __floats2half2_rn(x0, x1);
            __half2 p1 = __floats2half2_rn(x2, x3);
            *(uint32_t*)(smem + r0 * ROWB + col * 2)       = *(uint32_t*)&p0;
            *(uint32_t*)(smem + (r0 + 8) * ROWB + col * 2) = *(uint32_t*)&p1;
        }
    }
    __syncthreads();

    // ---- linear GEMM (tap 27) ----
    #pragma unroll
    for (int mi = 0; mi < 2; mi++)
        #pragma unroll
        for (int nt = 0; nt < 8; nt++)
            #pragma unroll
            for (int r = 0; r < 4; r++) c[mi][nt][r] = 0.f;
    do_tap(0, 27);

    // ---- +bl, layernorm, store ----
    float sum[2][2] = {{0.f, 0.f}, {0.f, 0.f}};
    float sq [2][2] = {{0.f, 0.f}, {0.f, 0.f}};
    #pragma unroll
    for (int nt = 0; nt < 8; nt++) {
        const int col = nt * 8 + qp * 2;
        const float b0 = bl[col], b1 = bl[col + 1];
        #pragma unroll
        for (int mi = 0; mi < 2; mi++) {
            float y0 = c[mi][nt][0] + b0, y1 = c[mi][nt][1] + b1;
            float y2 = c[mi][nt][2] + b0, y3 = c[mi][nt][3] + b1;
            c[mi][nt][0] = y0; c[mi][nt][1] = y1;
            c[mi][nt][2] = y2; c[mi][nt][3] = y3;
            sum[mi][0] += y0 + y1;  sq[mi][0] += y0 * y0 + y1 * y1;
            sum[mi][1] += y2 + y3;  sq[mi][1] += y2 * y2 + y3 * y3;
        }
    }
    #pragma unroll
    for (int off = 1; off <= 2; off <<= 1) {
        #pragma unroll
        for (int mi = 0; mi < 2; mi++)
            #pragma unroll
            for (int h = 0; h < 2; h++) {
                sum[mi][h] += __shfl_xor_sync(0xffffffffu, sum[mi][h], off);
                sq [mi][h] += __shfl_xor_sync(0xffffffffu, sq [mi][h], off);
            }
    }
    float mu[2][2], rs[2][2];
    #pragma unroll
    for (int mi = 0; mi < 2; mi++)
        #pragma unroll
        for (int h = 0; h < 2; h++) {
            float m = sum[mi][h] * (1.0f / 64.0f);
            float v = sq[mi][h] * (1.0f / 64.0f) - m * m;
            mu[mi][h] = m;
            rs[mi][h] = rsqrtf(v + LN_EPS);
        }
    const int base_row = blockIdx.x * NTHREADS + w * 32 + group;
    #pragma unroll
    for (int nt = 0; nt < 8; nt++) {
        const int col = nt * 8 + qp * 2;
        const float g0 = gamma[col], g1 = gamma[col + 1];
        const float be0 = beta[col], be1 = beta[col + 1];
        #pragma unroll
        for (int mi = 0; mi < 2; mi++) {
            int r0 = base_row + mi * 16;
            int r1 = r0 + 8;
            if (r0 < N_VOX) {
                float2 o;
                o.x = g0 * (c[mi][nt][0] - mu[mi][0]) * rs[mi][0] + be0;
                o.y = g1 * (c[mi][nt][1] - mu[mi][0]) * rs[mi][0] + be1;
                *(float2*)(out + (size_t)r0 * 64 + col) = o;
            }
            if (r1 < N_VOX) {
                float2 o;
                o.x = g0 * (c[mi][nt][2] - mu[mi][1]) * rs[mi][1] + be0;
                o.y = g1 * (c[mi][nt][3] - mu[mi][1]) * rs[mi][1] + be1;
                *(float2*)(out + (size_t)r1 * 64 + col) = o;
            }
        }
    }
}

// ---------- launch ----------
extern "C" void kernel_launch(void* const* d_in, const int* in_sizes, int n_in,
                              void* d_out, int out_size)
{
    const float* feats = (const float*)d_in[0];
    const int*   nb    = (const int*)d_in[1];
    const float* Wc    = (const float*)d_in[2];
    const float* bc    = (const float*)d_in[3];
    const float* Wl    = (const float*)d_in[4];
    const float* bl    = (const float*)d_in[5];
    const float* gamma = (const float*)d_in[6];
    const float* beta  = (const float*)d_in[7];
    float* out = (float*)d_out;

    static int init = 0;
    if (!init) {
        cudaFuncSetAttribute(conv_mma_kernel,
                             cudaFuncAttributeMaxDynamicSharedMemorySize, SMEM_BYTES);
        init = 1;
    }
    prep_feats<<<(N_VOX * 8 + 255) / 256, 256>>>(feats);
    prep_wfB<<<(28 * 2048 + 255) / 256, 256>>>(Wc, Wl);
    conv_mma_kernel<<<GRID_M, NTHREADS, SMEM_BYTES>>>(nb, bc, bl, gamma, beta, out);
}

// round 14
// speedup vs baseline: 1.1452x; 1.1452x over previous
#include <cuda_runtime.h>
#include <cuda_fp16.h>
#include <cstdint>

#define N_VOX    100000
#define NK       27
#define LN_EPS   1e-5f
#define NTHREADS 128
#define GRID_M   ((N_VOX + 127) / 128)   // 782

#define ROWB     144                     // A row stride bytes (72 halves)
#define STG_B    2304                    // 16 rows * 144

// Shared layout (bytes), total 53248 -> occ 4:
//  accS   [128][68] fp32                : 0     .. 34816
//  regionB (34816..53248), sparse phase:
//    stages 4 x 2304                    : +0    (9216)
//    slotV  26*32 int                   : +9216 (3328)
//    slotI  26*32 int                   : +12544(3328)
//    warpcnt 4*26 int                   : +15872(416)
//    woff    26*4 int                   : +16288(416)
//    cntS    26 int (pad 128)           : +16704
//    desc    64 int                     : +16832(256)
//    ndesc   1 int                      : +17088
//  regionB, dense phase: center/linear A tile 128*144 = 18432 @ +0
#define RB        34816
#define STG_OFF   (RB + 0)
#define SLOTV_OFF (RB + 9216)
#define SLOTI_OFF (RB + 12544)
#define WCNT_OFF  (RB + 15872)
#define WOFF_OFF  (RB + 16288)
#define CNTS_OFF  (RB + 16704)
#define DESC_OFF  (RB + 16832)
#define NDESC_OFF (RB + 17088)
#define CENTA_OFF RB
#define SMEM_BYTES 53248

__device__ __align__(16) __half    g_f16[N_VOX * 64];
// B fragments: [tap][nt][lane][8 regs]; reg r = k4*2+bsel,
// value = half2(W[k][n], W[k+1][n]) with n = nt*8+group, k = k4*16+qp*2+bsel*8
__device__ __align__(16) uint32_t  g_wfB[28 * 8 * 32 * 8];
__device__ __align__(16) __half    g_w16[28 * 4096];   // [tap][cout][cin] (fallback only)

// ---------- helpers ----------
__device__ __forceinline__ uint32_t smem_u32(const void* p) {
    uint32_t a;
    asm("{ .reg .u64 t; cvta.to.shared.u64 t, %1; cvt.u32.u64 %0, t; }" : "=r"(a) : "l"(p));
    return a;
}
__device__ __forceinline__ void cpa16(uint32_t dst, const void* src) {
    asm volatile("cp.async.cg.shared.global [%0], [%1], 16;" :: "r"(dst), "l"(src));
}
#define CP_COMMIT()  asm volatile("cp.async.commit_group;" ::: "memory")
#define CP_WAIT(n)   asm volatile("cp.async.wait_group %0;" :: "n"(n) : "memory")

__device__ __forceinline__ void ldsm4(uint32_t* r, uint32_t addr) {
    asm volatile("ldmatrix.sync.aligned.m8n8.x4.shared.b16 {%0,%1,%2,%3}, [%4];"
                 : "=r"(r[0]), "=r"(r[1]), "=r"(r[2]), "=r"(r[3]) : "r"(addr));
}
__device__ __forceinline__ void mma16816(float* c, const uint32_t* a,
                                         uint32_t b0, uint32_t b1) {
    asm volatile(
        "mma.sync.aligned.m16n8k16.row.col.f32.f16.f16.f32 "
        "{%0,%1,%2,%3}, {%4,%5,%6,%7}, {%8,%9}, {%0,%1,%2,%3};"
        : "+f"(c[0]), "+f"(c[1]), "+f"(c[2]), "+f"(c[3])
        : "r"(a[0]), "r"(a[1]), "r"(a[2]), "r"(a[3]), "r"(b0), "r"(b1));
}

// ---------- pre-kernels ----------
__global__ void prep_feats(const float* __restrict__ feats) {
    int t = blockIdx.x * blockDim.x + threadIdx.x;
    if (t >= N_VOX * 8) return;
    const float4* F = (const float4*)feats;
    float4 f0 = F[t * 2], f1 = F[t * 2 + 1];
    __half2 h0 = __floats2half2_rn(f0.x, f0.y);
    __half2 h1 = __floats2half2_rn(f0.z, f0.w);
    __half2 h2 = __floats2half2_rn(f1.x, f1.y);
    __half2 h3 = __floats2half2_rn(f1.z, f1.w);
    uint4 o;
    o.x = *(uint32_t*)&h0; o.y = *(uint32_t*)&h1;
    o.z = *(uint32_t*)&h2; o.w = *(uint32_t*)&h3;
    ((uint4*)g_f16)[t] = o;
}
__global__ void prep_w(const float* __restrict__ Wc, const float* __restrict__ Wl) {
    int e = blockIdx.x * blockDim.x + threadIdx.x;
    if (e < 28 * 2048) {
        // fragment layout
        int r    = e & 7;
        int lane = (e >> 3) & 31;
        int nt   = (e >> 8) & 7;
        int tap  = e >> 11;
        int group = lane >> 2, qp = lane & 3;
        int k4 = r >> 1, bsel = r & 1;
        int n = nt * 8 + group;
        int k = k4 * 16 + qp * 2 + bsel * 8;
        float w0, w1;
        if (tap < 27) { w0 = Wc[tap * 4096 + k * 64 + n]; w1 = Wc[tap * 4096 + (k + 1) * 64 + n]; }
        else          { w0 = Wl[k * 64 + n];              w1 = Wl[(k + 1) * 64 + n]; }
        __half2 p = __floats2half2_rn(w0, w1);
        g_wfB[e] = *(uint32_t*)&p;
    } else {
        int e2 = e - 28 * 2048;
        if (e2 >= 28 * 4096) return;
        int tap = e2 >> 12, rem = e2 & 4095;
        int o = rem >> 6, cc = rem & 63;
        float w = (tap < 27) ? Wc[tap * 4096 + cc * 64 + o] : Wl[cc * 64 + o];
        g_w16[e2] = __float2half_rn(w);
    }
}

// ---------- main ----------
__global__ __launch_bounds__(NTHREADS, 4)
void conv_mma_kernel(const int* __restrict__ nb, const float* __restrict__ bc,
                     const float* __restrict__ bl, const float* __restrict__ gamma,
                     const float* __restrict__ beta, float* __restrict__ out)
{
    extern __shared__ __align__(16) char smem[];
    const uint32_t sb = smem_u32(smem);
    float* accS  = (float*)smem;
    int* slotV   = (int*)(smem + SLOTV_OFF);
    int* slotI   = (int*)(smem + SLOTI_OFF);
    int* warpcnt = (int*)(smem + WCNT_OFF);
    int* woff    = (int*)(smem + WOFF_OFF);
    int* cntS    = (int*)(smem + CNTS_OFF);
    int* descS   = (int*)(smem + DESC_OFF);
    int* ndescS  = (int*)(smem + NDESC_OFF);

    const int tid   = threadIdx.x;
    const int lane  = tid & 31;
    const int w     = tid >> 5;
    const int group = lane >> 2;
    const int qp    = lane & 3;
    const int gvox  = blockIdx.x * NTHREADS + tid;
    const bool active = gvox < N_VOX;
    const int* nrow = nb + (long)gvox * NK;
    const unsigned lmask = (1u << lane) - 1u;

    // ---- zero accS (128*68 fp32 = 2176 uint4) ----
    {
        uint4 z = make_uint4(0, 0, 0, 0);
        #pragma unroll
        for (int t = 0; t < 17; t++) ((uint4*)smem)[tid + t * NTHREADS] = z;
    }

    // ---- phase 1a: per-warp per-tap counts ----
    #pragma unroll 1
    for (int kk = 0; kk < 26; kk++) {
        int k = kk + (kk >= 13 ? 1 : 0);
        bool valid = active && (nrow[k] >= 0);
        unsigned bal = __ballot_sync(0xffffffffu, valid);
        if (lane == 0) warpcnt[w * 26 + kk] = __popc(bal);
    }
    __syncthreads();
    // offsets + totals
    if (tid < 26) {
        int c0 = warpcnt[0 * 26 + tid], c1 = warpcnt[1 * 26 + tid];
        int c2 = warpcnt[2 * 26 + tid], c3 = warpcnt[3 * 26 + tid];
        woff[tid * 4 + 0] = 0;
        woff[tid * 4 + 1] = c0;
        woff[tid * 4 + 2] = c0 + c1;
        woff[tid * 4 + 3] = c0 + c1 + c2;
        cntS[tid] = c0 + c1 + c2 + c3;
    }
    __syncthreads();
    // descriptor list (thread 0)
    if (tid == 0) {
        int nd = 0;
        for (int kk = 0; kk < 26; kk++) {
            int cn = cntS[kk]; if (cn > 32) cn = 32;
            for (int b = 0; b < cn; b += 16) descS[nd++] = kk * 256 + b;
        }
        *ndescS = nd;
    }
    // ---- phase 1b: fill slot lists ----
    unsigned ovf = 0;
    #pragma unroll 1
    for (int kk = 0; kk < 26; kk++) {
        int k = kk + (kk >= 13 ? 1 : 0);
        int idx = active ? nrow[k] : -1;
        bool valid = idx >= 0;
        unsigned bal = __ballot_sync(0xffffffffu, valid);
        if (valid) {
            int pos = woff[kk * 4 + w] + __popc(bal & lmask);
            if (pos < 32) { slotV[kk * 32 + pos] = tid; slotI[kk * 32 + pos] = idx; }
            else ovf |= 1u << kk;
        }
    }
    __syncthreads();
    const int ndesc = *ndescS;

    // ---- sparse tile pipeline: 4 stages, one sync per tile ----
    auto gatherT = [&](int stg, int d) {
        int kk = d >> 8, base = d & 255;
        int kcnt = cntS[kk]; if (kcnt > 32) kcnt = 32;
        int s = base + (tid >> 3), j = tid & 7;
        uint32_t doff = STG_OFF + stg * STG_B + (tid >> 3) * ROWB + j * 16;
        if (s < kcnt) {
            const char* src = (const char*)(g_f16 + (size_t)slotI[kk * 32 + s] * 64) + j * 16;
            cpa16(sb + doff, src);
        } else {
            *(uint4*)(smem + doff) = make_uint4(0, 0, 0, 0);
        }
    };

    if (ndesc > 0) gatherT(0, descS[0]);
    CP_COMMIT();
    if (ndesc > 1) gatherT(1, descS[1]);
    CP_COMMIT();

    #pragma unroll 1
    for (int i = 0; i < ndesc; i++) {
        if (i + 1 < ndesc) CP_WAIT(1); else CP_WAIT(0);
        __syncthreads();
        if (i + 2 < ndesc) { gatherT((i + 2) & 3, descS[i + 2]); CP_COMMIT(); }

        const int d = descS[i];
        const int kk = d >> 8, base = d & 255;
        const int k = kk + (kk >= 13 ? 1 : 0);
        int kcnt = cntS[kk]; if (kcnt > 32) kcnt = 32;

        uint32_t a[4][4];
        const uint32_t lmb = sb + STG_OFF + (i & 3) * STG_B
                           + (lane & 15) * ROWB + (lane >> 4) * 16;
        #pragma unroll
        for (int k4 = 0; k4 < 4; k4++) ldsm4(a[k4], lmb + k4 * 32);

        float c8[2][4];
        #pragma unroll
        for (int nti = 0; nti < 2; nti++)
            #pragma unroll
            for (int r = 0; r < 4; r++) c8[nti][r] = 0.f;

        #pragma unroll
        for (int nti = 0; nti < 2; nti++) {
            const int nt = 2 * w + nti;
            const uint4* wf = (const uint4*)(g_wfB + (((size_t)k * 8 + nt) * 32 + lane) * 8);
            uint4 b01 = wf[0], b23 = wf[1];
            mma16816(c8[nti], a[0], b01.x, b01.y);
            mma16816(c8[nti], a[1], b01.z, b01.w);
            mma16816(c8[nti], a[2], b23.x, b23.y);
            mma16816(c8[nti], a[3], b23.z, b23.w);
        }

        // scatter: plain smem RMW (warp owns cols [16w,16w+16); no collisions)
        const int s0 = base + group, s1 = s0 + 8;
        const int v0 = (s0 < kcnt) ? slotV[kk * 32 + s0] : -1;
        const int v1 = (s1 < kcnt) ? slotV[kk * 32 + s1] : -1;
        #pragma unroll
        for (int nti = 0; nti < 2; nti++) {
            const int col = (2 * w + nti) * 8 + qp * 2;
            if (v0 >= 0) {
                float* p = accS + v0 * 68 + col;
                p[0] += c8[nti][0]; p[1] += c8[nti][1];
            }
            if (v1 >= 0) {
                float* p = accS + v1 * 68 + col;
                p[0] += c8[nti][2]; p[1] += c8[nti][3];
            }
        }
    }
    // overflow fallback (P ~ 1e-15; per-thread, own accS row -> no races)
    if (ovf) {
        #pragma unroll 1
        for (int kk = 0; kk < 26; kk++) if (ovf & (1u << kk)) {
            int k = kk + (kk >= 13 ? 1 : 0);
            const __half* f = g_f16 + (size_t)nrow[k] * 64;
            for (int o = 0; o < 64; o++) {
                float s = 0.f;
                for (int cc = 0; cc < 64; cc++)
                    s += __half2float(f[cc]) * __half2float(g_w16[k * 4096 + o * 64 + cc]);
                accS[tid * 68 + o] += s;
            }
        }
    }
    __syncthreads();   // sparse done; regionB becomes center A tile

    // ---- center tap: gather full 128-row tile ----
    {
        int idx = active ? nrow[13] : -1;
        uint32_t doff = CENTA_OFF + tid * ROWB;
        if (idx >= 0) {
            const char* src = (const char*)(g_f16 + (size_t)idx * 64);
            #pragma unroll
            for (int j = 0; j < 8; j++) cpa16(sb + doff + j * 16, src + j * 16);
        } else {
            uint4 z = make_uint4(0, 0, 0, 0);
            #pragma unroll
            for (int j = 0; j < 8; j++) *(uint4*)(smem + doff + j * 16) = z;
        }
    }
    CP_COMMIT(); CP_WAIT(0);
    __syncthreads();

    float c[2][8][4];
    #pragma unroll
    for (int mi = 0; mi < 2; mi++)
        #pragma unroll
        for (int nt = 0; nt < 8; nt++)
            #pragma unroll
            for (int r = 0; r < 4; r++) c[mi][nt][r] = 0.f;

    const uint32_t lmC = sb + CENTA_OFF + (w * 32 + (lane & 15)) * ROWB + (lane >> 4) * 16;
    auto denseGEMM = [&](int tap) {
        uint32_t a[2][4][4];
        #pragma unroll
        for (int mi = 0; mi < 2; mi++)
            #pragma unroll
            for (int k4 = 0; k4 < 4; k4++)
                ldsm4(a[mi][k4], lmC + mi * 16 * ROWB + k4 * 32);
        const uint4* wf = (const uint4*)(g_wfB + (((size_t)tap * 8) * 32 + lane) * 8);
        #pragma unroll
        for (int nt = 0; nt < 8; nt++) {
            uint4 b01 = wf[nt * 64];
            uint4 b23 = wf[nt * 64 + 1];
            mma16816(c[0][nt], a[0][0], b01.x, b01.y);
            mma16816(c[1][nt], a[1][0], b01.x, b01.y);
            mma16816(c[0][nt], a[0][1], b01.z, b01.w);
            mma16816(c[1][nt], a[1][1], b01.z, b01.w);
            mma16816(c[0][nt], a[0][2], b23.x, b23.y);
            mma16816(c[1][nt], a[1][2], b23.x, b23.y);
            mma16816(c[0][nt], a[0][3], b23.z, b23.w);
            mma16816(c[1][nt], a[1][3], b23.z, b23.w);
        }
    };
    denseGEMM(13);
    __syncthreads();   // center A reads complete before X overwrites

    // ---- merge accS + bc, write X fp16 into CENTA ----
    #pragma unroll
    for (int nt = 0; nt < 8; nt++) {
        const int col = nt * 8 + qp * 2;
        const float b0 = bc[col], b1 = bc[col + 1];
        #pragma unroll
        for (int mi = 0; mi < 2; mi++) {
            const int r0 = w * 32 + mi * 16 + group;
            float x0 = c[mi][nt][0] + b0 + accS[r0 * 68 + col];
            float x1 = c[mi][nt][1] + b1 + accS[r0 * 68 + col + 1];
            float x2 = c[mi][nt][2] + b0 + accS[(r0 + 8) * 68 + col];
            float x3 = c[mi][nt][3] + b1 + accS[(r0 + 8) * 68 + col + 1];
            __half2 p0 = __floats2half2_rn(x0, x1);
            __half2 p1 = __floats2half2_rn(x2, x3);
            *(uint32_t*)(smem + CENTA_OFF + r0 * ROWB + col * 2)       = *(uint32_t*)&p0;
            *(uint32_t*)(smem + CENTA_OFF + (r0 + 8) * ROWB + col * 2) = *(uint32_t*)&p1;
        }
    }
    __syncthreads();

    // ---- linear GEMM (tap 27) ----
    #pragma unroll
    for (int mi = 0; mi < 2; mi++)
        #pragma unroll
        for (int nt = 0; nt < 8; nt++)
            #pragma unroll
            for (int r = 0; r < 4; r++) c[mi][nt][r] = 0.f;
    denseGEMM(27);

    // ---- +bl, layernorm, store ----
    float sum[2][2] = {{0.f, 0.f}, {0.f, 0.f}};
    float sq [2][2] = {{0.f, 0.f}, {0.f, 0.f}};
    #pragma unroll
    for (int nt = 0; nt < 8; nt++) {
        const int col = nt * 8 + qp * 2;
        const float b0 = bl[col], b1 = bl[col + 1];
        #pragma unroll
        for (int mi = 0; mi < 2; mi++) {
            float y0 = c[mi][nt][0] + b0, y1 = c[mi][nt][1] + b1;
            float y2 = c[mi][nt][2] + b0, y3 = c[mi][nt][3] + b1;
            c[mi][nt][0] = y0; c[mi][nt][1] = y1;
            c[mi][nt][2] = y2; c[mi][nt][3] = y3;
            sum[mi][0] += y0 + y1;  sq[mi][0] += y0 * y0 + y1 * y1;
            sum[mi][1] += y2 + y3;  sq[mi][1] += y2 * y2 + y3 * y3;
        }
    }
    #pragma unroll
    for (int off = 1; off <= 2; off <<= 1) {
        #pragma unroll
        for (int mi = 0; mi < 2; mi++)
            #pragma unroll
            for (int h = 0; h < 2; h++) {
                sum[mi][h] += __shfl_xor_sync(0xffffffffu, sum[mi][h], off);
                sq [mi][h] += __shfl_xor_sync(0xffffffffu, sq [mi][h], off);
            }
    }
    float mu[2][2], rs[2][2];
    #pragma unroll
    for (int mi = 0; mi < 2; mi++)
        #pragma unroll
        for (int h = 0; h < 2; h++) {
            float m = sum[mi][h] * (1.0f / 64.0f);
            float v = sq[mi][h] * (1.0f / 64.0f) - m * m;
            mu[mi][h] = m;
            rs[mi][h] = rsqrtf(v + LN_EPS);
        }
    const int base_row = blockIdx.x * NTHREADS + w * 32 + group;
    #pragma unroll
    for (int nt = 0; nt < 8; nt++) {
        const int col = nt * 8 + qp * 2;
        const float g0 = gamma[col], g1 = gamma[col + 1];
        const float be0 = beta[col], be1 = beta[col + 1];
        #pragma unroll
        for (int mi = 0; mi < 2; mi++) {
            int r0 = base_row + mi * 16;
            int r1 = r0 + 8;
            if (r0 < N_VOX) {
                float2 o;
                o.x = g0 * (c[mi][nt][0] - mu[mi][0]) * rs[mi][0] + be0;
                o.y = g1 * (c[mi][nt][1] - mu[mi][0]) * rs[mi][0] + be1;
                *(float2*)(out + (size_t)r0 * 64 + col) = o;
            }
            if (r1 < N_VOX) {
                float2 o;
                o.x = g0 * (c[mi][nt][2] - mu[mi][1]) * rs[mi][1] + be0;
                o.y = g1 * (c[mi][nt][3] - mu[mi][1]) * rs[mi][1] + be1;
                *(float2*)(out + (size_t)r1 * 64 + col) = o;
            }
        }
    }
}

// ---------- launch ----------
extern "C" void kernel_launch(void* const* d_in, const int* in_sizes, int n_in,
                              void* d_out, int out_size)
{
    const float* feats = (const float*)d_in[0];
    const int*   nb    = (const int*)d_in[1];
    const float* Wc    = (const float*)d_in[2];
    const float* bc    = (const float*)d_in[3];
    const float* Wl    = (const float*)d_in[4];
    const float* bl    = (const float*)d_in[5];
    const float* gamma = (const float*)d_in[6];
    const float* beta  = (const float*)d_in[7];
    float* out = (float*)d_out;

    static int init = 0;
    if (!init) {
        cudaFuncSetAttribute(conv_mma_kernel,
                             cudaFuncAttributeMaxDynamicSharedMemorySize, SMEM_BYTES);
        init = 1;
    }
    prep_feats<<<(N_VOX * 8 + 255) / 256, 256>>>(feats);
    prep_w<<<(28 * 2048 + 28 * 4096 + 255) / 256, 256>>>(Wc, Wl);
    conv_mma_kernel<<<GRID_M, NTHREADS, SMEM_BYTES>>>(nb, bc, bl, gamma, beta, out);
}

// round 15
// speedup vs baseline: 1.2230x; 1.0679x over previous
#include <cuda_runtime.h>
#include <cuda_fp16.h>
#include <cstdint>

#define N_VOX    100000
#define NK       27
#define LN_EPS   1e-5f
#define NTHREADS 256
#define TILE_M   256
#define GRID_M   ((N_VOX + TILE_M - 1) / TILE_M)   // 391

// smem stage: A 256x(64+8 pad) fp16 = 36864B ; W 64x(64+8) fp16 = 9216B
#define ROWB    144                      // row stride bytes (72 fp16)
#define A_BYTES 36864
#define STAGE   46080
#define SMEM_BYTES (2 * STAGE)           // 92160 -> occ 2 (16 warps/SM)

// Precomputed fp16 data (static device globals, no allocation)
__device__ __align__(16) __half g_f16[N_VOX * 64];
__device__ __align__(16) __half g_w16[28 * 4096];   // [tap][cout][cin], tap27 = W_lin

// ---------- helpers ----------
__device__ __forceinline__ uint32_t smem_u32(const void* p) {
    uint32_t a;
    asm("{ .reg .u64 t; cvta.to.shared.u64 t, %1; cvt.u32.u64 %0, t; }" : "=r"(a) : "l"(p));
    return a;
}
__device__ __forceinline__ uint32_t lds32(uint32_t a) {
    uint32_t v;
    asm volatile("ld.shared.b32 %0, [%1];" : "=r"(v) : "r"(a));
    return v;
}
__device__ __forceinline__ void sts32(uint32_t a, uint32_t v) {
    asm volatile("st.shared.b32 [%0], %1;" :: "r"(a), "r"(v));
}
__device__ __forceinline__ void cpa16(uint32_t dst, const void* src) {
    asm volatile("cp.async.cg.shared.global [%0], [%1], 16;" :: "r"(dst), "l"(src));
}
#define CP_COMMIT()  asm volatile("cp.async.commit_group;" ::: "memory")
#define CP_WAIT(n)   asm volatile("cp.async.wait_group %0;" :: "n"(n) : "memory")

__device__ __forceinline__ void mma16816(float* c, const uint32_t* a,
                                         uint32_t b0, uint32_t b1) {
    asm volatile(
        "mma.sync.aligned.m16n8k16.row.col.f32.f16.f16.f32 "
        "{%0,%1,%2,%3}, {%4,%5,%6,%7}, {%8,%9}, {%0,%1,%2,%3};"
        : "+f"(c[0]), "+f"(c[1]), "+f"(c[2]), "+f"(c[3])
        : "r"(a[0]), "r"(a[1]), "r"(a[2]), "r"(a[3]), "r"(b0), "r"(b1));
}

// ---------- merged pre-kernel ----------
#define FEAT_BLOCKS 3125                 // N_VOX*8 / 256
#define W_BLOCKS    448                  // 28*4096 / 256

__global__ void prep_all(const float* __restrict__ feats,
                         const float* __restrict__ Wc, const float* __restrict__ Wl) {
    int b = blockIdx.x;
    if (b < FEAT_BLOCKS) {
        int t = b * blockDim.x + threadIdx.x;      // 8 floats / thread
        if (t >= N_VOX * 8) return;
        const float4* F = (const float4*)feats;
        float4 f0 = F[t * 2], f1 = F[t * 2 + 1];
        __half2 h0 = __floats2half2_rn(f0.x, f0.y);
        __half2 h1 = __floats2half2_rn(f0.z, f0.w);
        __half2 h2 = __floats2half2_rn(f1.x, f1.y);
        __half2 h3 = __floats2half2_rn(f1.z, f1.w);
        uint4 o;
        o.x = *(uint32_t*)&h0; o.y = *(uint32_t*)&h1;
        o.z = *(uint32_t*)&h2; o.w = *(uint32_t*)&h3;
        ((uint4*)g_f16)[t] = o;
    } else {
        int e = (b - FEAT_BLOCKS) * blockDim.x + threadIdx.x;   // (tap, o, c)
        if (e >= 28 * 4096) return;
        int k = e >> 12, rem = e & 4095;
        int o = rem >> 6, c = rem & 63;
        float w = (k < 27) ? Wc[k * 4096 + c * 64 + o] : Wl[c * 64 + o];
        g_w16[e] = __float2half_rn(w);
    }
}

// ---------- main ----------
__global__ __launch_bounds__(NTHREADS, 2)
void conv_mma_kernel(const int* __restrict__ nb, const float* __restrict__ bc,
                     const float* __restrict__ bl, const float* __restrict__ gamma,
                     const float* __restrict__ beta, float* __restrict__ out)
{
    extern __shared__ __align__(16) char smem[];
    const uint32_t sb = smem_u32(smem);
    const int tid  = threadIdx.x;
    const int lane = tid & 31;
    const int w    = tid >> 5;       // 0..7
    const int group = lane >> 2;     // 0..7
    const int qp    = lane & 3;      // 0..3
    const int gvox = blockIdx.x * TILE_M + tid;
    const bool active = gvox < N_VOX;
    const int* nrow = nb + (long)gvox * NK;

    float c[2][8][4];
    #pragma unroll
    for (int mi = 0; mi < 2; mi++)
        #pragma unroll
        for (int nt = 0; nt < 8; nt++)
            #pragma unroll
            for (int r = 0; r < 4; r++) c[mi][nt][r] = 0.0f;

    // ---- issue helpers ----
    auto issueA = [&](int s, int k) {
        uint32_t dst = sb + s * STAGE + tid * ROWB;
        int idx = active ? nrow[k] : -1;
        if (idx >= 0) {
            const char* src = (const char*)(g_f16 + (size_t)idx * 64);
            #pragma unroll
            for (int j = 0; j < 8; j++) cpa16(dst + j * 16, src + j * 16);
        } else {
            float4 z = make_float4(0.f, 0.f, 0.f, 0.f);
            #pragma unroll
            for (int j = 0; j < 8; j++)
                *(float4*)(smem + s * STAGE + tid * ROWB + j * 16) = z;
        }
    };
    auto issueW = [&](uint32_t wbase, int k) {
        const char* srcb = (const char*)(g_w16 + (size_t)k * 4096);
        #pragma unroll
        for (int t = 0; t < 2; t++) {
            int ch = tid + t * NTHREADS;     // 512 chunks of 16B
            int row = ch >> 3, j = ch & 7;
            cpa16(wbase + row * ROWB + j * 16, srcb + ch * 16);
        }
    };
    auto do_tap = [&](uint32_t Ab, uint32_t Wb) {
        #pragma unroll
        for (int k4 = 0; k4 < 4; k4++) {
            const int k0 = k4 * 16;
            uint32_t a[2][4];
            #pragma unroll
            for (int mi = 0; mi < 2; mi++) {
                uint32_t base = Ab + (w * 32 + mi * 16 + group) * ROWB + (k0 + qp * 2) * 2;
                a[mi][0] = lds32(base);
                a[mi][1] = lds32(base + 8 * ROWB);
                a[mi][2] = lds32(base + 16);
                a[mi][3] = lds32(base + 8 * ROWB + 16);
            }
            #pragma unroll
            for (int nt = 0; nt < 8; nt++) {
                uint32_t baddr = Wb + (nt * 8 + group) * ROWB + (k0 + qp * 2) * 2;
                uint32_t b0 = lds32(baddr);
                uint32_t b1 = lds32(baddr + 16);
                mma16816(c[0][nt], a[0], b0, b1);
                mma16816(c[1][nt], a[1], b0, b1);
            }
        }
    };

    // ---- prologue: taps 0,1 ----
    issueA(0, 0); issueW(sb + 0 * STAGE + A_BYTES, 0); CP_COMMIT();
    issueA(1, 1); issueW(sb + 1 * STAGE + A_BYTES, 1); CP_COMMIT();

    // ---- conv mainloop ----
    #pragma unroll 1
    for (int k = 0; k < NK; k++) {
        const int s = k & 1;
        if (k < NK - 1) CP_WAIT(1); else CP_WAIT(0);
        __syncthreads();
        do_tap(sb + s * STAGE, sb + s * STAGE + A_BYTES);
        __syncthreads();
        if (k + 2 < NK) {
            issueA(s, k + 2);
            issueW(sb + s * STAGE + A_BYTES, k + 2);
            CP_COMMIT();
        }
    }

    // ---- epilogue: +bc, convert to fp16 X in stage0 A; load W_lin ----
    issueW(sb + A_BYTES, 27); CP_COMMIT();
    #pragma unroll
    for (int nt = 0; nt < 8; nt++) {
        const int col0 = nt * 8 + qp * 2;
        const float b0 = bc[col0], b1 = bc[col0 + 1];
        #pragma unroll
        for (int mi = 0; mi < 2; mi++) {
            float x0 = c[mi][nt][0] + b0;
            float x1 = c[mi][nt][1] + b1;
            float x2 = c[mi][nt][2] + b0;
            float x3 = c[mi][nt][3] + b1;
            __half2 p0 = __floats2half2_rn(x0, x1);
            __half2 p1 = __floats2half2_rn(x2, x3);
            const int r0 = w * 32 + mi * 16 + group;
            sts32(sb + r0 * ROWB + col0 * 2, *(uint32_t*)&p0);
            sts32(sb + (r0 + 8) * ROWB + col0 * 2, *(uint32_t*)&p1);
        }
    }
    CP_WAIT(0);
    __syncthreads();

    // ---- linear GEMM (tap 27) ----
    #pragma unroll
    for (int mi = 0; mi < 2; mi++)
        #pragma unroll
        for (int nt = 0; nt < 8; nt++)
            #pragma unroll
            for (int r = 0; r < 4; r++) c[mi][nt][r] = 0.0f;
    do_tap(sb, sb + A_BYTES);

    // ---- +bl, layernorm in registers ----
    float sum[2][2] = {{0.f, 0.f}, {0.f, 0.f}};
    float sq [2][2] = {{0.f, 0.f}, {0.f, 0.f}};
    #pragma unroll
    for (int nt = 0; nt < 8; nt++) {
        const int col0 = nt * 8 + qp * 2;
        const float b0 = bl[col0], b1 = bl[col0 + 1];
        #pragma unroll
        for (int mi = 0; mi < 2; mi++) {
            float y0 = c[mi][nt][0] + b0, y1 = c[mi][nt][1] + b1;
            float y2 = c[mi][nt][2] + b0, y3 = c[mi][nt][3] + b1;
            c[mi][nt][0] = y0; c[mi][nt][1] = y1;
            c[mi][nt][2] = y2; c[mi][nt][3] = y3;
            sum[mi][0] += y0 + y1;            sq[mi][0] += y0 * y0 + y1 * y1;
            sum[mi][1] += y2 + y3;            sq[mi][1] += y2 * y2 + y3 * y3;
        }
    }
    #pragma unroll
    for (int off = 1; off <= 2; off <<= 1) {
        #pragma unroll
        for (int mi = 0; mi < 2; mi++)
            #pragma unroll
            for (int h = 0; h < 2; h++) {
                sum[mi][h] += __shfl_xor_sync(0xffffffffu, sum[mi][h], off);
                sq [mi][h] += __shfl_xor_sync(0xffffffffu, sq [mi][h], off);
            }
    }
    float mu[2][2], rs[2][2];
    #pragma unroll
    for (int mi = 0; mi < 2; mi++)
        #pragma unroll
        for (int h = 0; h < 2; h++) {
            float m = sum[mi][h] * (1.0f / 64.0f);
            float v = sq[mi][h] * (1.0f / 64.0f) - m * m;
            mu[mi][h] = m;
            rs[mi][h] = rsqrtf(v + LN_EPS);
        }
    const int base_row = blockIdx.x * TILE_M + w * 32 + group;
    #pragma unroll
    for (int nt = 0; nt < 8; nt++) {
        const int col0 = nt * 8 + qp * 2;
        const float g0 = gamma[col0], g1 = gamma[col0 + 1];
        const float be0 = beta[col0], be1 = beta[col0 + 1];
        #pragma unroll
        for (int mi = 0; mi < 2; mi++) {
            int r0 = base_row + mi * 16;
            int r1 = r0 + 8;
            if (r0 < N_VOX) {
                float2 o;
                o.x = g0 * (c[mi][nt][0] - mu[mi][0]) * rs[mi][0] + be0;
                o.y = g1 * (c[mi][nt][1] - mu[mi][0]) * rs[mi][0] + be1;
                *(float2*)(out + (size_t)r0 * 64 + col0) = o;
            }
            if (r1 < N_VOX) {
                float2 o;
                o.x = g0 * (c[mi][nt][2] - mu[mi][1]) * rs[mi][1] + be0;
                o.y = g1 * (c[mi][nt][3] - mu[mi][1]) * rs[mi][1] + be1;
                *(float2*)(out + (size_t)r1 * 64 + col0) = o;
            }
        }
    }
}

// ---------- launch ----------
extern "C" void kernel_launch(void* const* d_in, const int* in_sizes, int n_in,
                              void* d_out, int out_size)
{
    const float* feats = (const float*)d_in[0];
    const int*   nb    = (const int*)d_in[1];
    const float* Wc    = (const float*)d_in[2];
    const float* bc    = (const float*)d_in[3];
    const float* Wl    = (const float*)d_in[4];
    const float* bl    = (const float*)d_in[5];
    const float* gamma = (const float*)d_in[6];
    const float* beta  = (const float*)d_in[7];
    float* out = (float*)d_out;

    static int init = 0;
    if (!init) {
        cudaFuncSetAttribute(conv_mma_kernel,
                             cudaFuncAttributeMaxDynamicSharedMemorySize, SMEM_BYTES);
        init = 1;
    }
    prep_all<<<FEAT_BLOCKS + W_BLOCKS, 256>>>(feats, Wc, Wl);
    conv_mma_kernel<<<GRID_M, NTHREADS, SMEM_BYTES>>>(nb, bc, bl, gamma, beta, out);
}

// round 16
// speedup vs baseline: 1.2548x; 1.0260x over previous
#include <cuda_runtime.h>
#include <cuda_fp16.h>
#include <cstdint>

#define N_VOX    100000
#define NK       27
#define LN_EPS   1e-5f
#define NTHREADS 256
#define TILE_M   256
#define GRID_M   ((N_VOX + TILE_M - 1) / TILE_M)   // 391

// smem stage: A 256x(64+8 pad) fp16 = 36864B ; W 64x(64+8) fp16 = 9216B
#define ROWB    144                      // row stride bytes (72 fp16)
#define A_BYTES 36864
#define STAGE   46080
#define SMEM_BYTES (2 * STAGE)           // 92160 -> occ 2 (16 warps/SM)

// Precomputed fp16 data (static device globals, no allocation)
__device__ __align__(16) __half g_f16[N_VOX * 64];
__device__ __align__(16) __half g_w16[28 * 4096];   // [tap][cout][cin], tap27 = W_lin

// ---------- helpers ----------
__device__ __forceinline__ uint32_t smem_u32(const void* p) {
    uint32_t a;
    asm("{ .reg .u64 t; cvta.to.shared.u64 t, %1; cvt.u32.u64 %0, t; }" : "=r"(a) : "l"(p));
    return a;
}
__device__ __forceinline__ uint32_t lds32(uint32_t a) {
    uint32_t v;
    asm volatile("ld.shared.b32 %0, [%1];" : "=r"(v) : "r"(a));
    return v;
}
__device__ __forceinline__ void sts32(uint32_t a, uint32_t v) {
    asm volatile("st.shared.b32 [%0], %1;" :: "r"(a), "r"(v));
}
__device__ __forceinline__ void cpa16(uint32_t dst, const void* src) {
    asm volatile("cp.async.cg.shared.global [%0], [%1], 16;" :: "r"(dst), "l"(src));
}
#define CP_COMMIT()  asm volatile("cp.async.commit_group;" ::: "memory")
#define CP_WAIT(n)   asm volatile("cp.async.wait_group %0;" :: "n"(n) : "memory")

__device__ __forceinline__ void mma16816(float* c, const uint32_t* a,
                                         uint32_t b0, uint32_t b1) {
    asm volatile(
        "mma.sync.aligned.m16n8k16.row.col.f32.f16.f16.f32 "
        "{%0,%1,%2,%3}, {%4,%5,%6,%7}, {%8,%9}, {%0,%1,%2,%3};"
        : "+f"(c[0]), "+f"(c[1]), "+f"(c[2]), "+f"(c[3])
        : "r"(a[0]), "r"(a[1]), "r"(a[2]), "r"(a[3]), "r"(b0), "r"(b1));
}

// ---------- merged pre-kernel ----------
#define FEAT_BLOCKS 3125                 // N_VOX*8 / 256
#define W_BLOCKS    448                  // 28*4096 / 256

__global__ void prep_all(const float* __restrict__ feats,
                         const float* __restrict__ Wc, const float* __restrict__ Wl) {
    int b = blockIdx.x;
    if (b < FEAT_BLOCKS) {
        int t = b * blockDim.x + threadIdx.x;      // 8 floats / thread
        if (t >= N_VOX * 8) return;
        const float4* F = (const float4*)feats;
        float4 f0 = F[t * 2], f1 = F[t * 2 + 1];
        __half2 h0 = __floats2half2_rn(f0.x, f0.y);
        __half2 h1 = __floats2half2_rn(f0.z, f0.w);
        __half2 h2 = __floats2half2_rn(f1.x, f1.y);
        __half2 h3 = __floats2half2_rn(f1.z, f1.w);
        uint4 o;
        o.x = *(uint32_t*)&h0; o.y = *(uint32_t*)&h1;
        o.z = *(uint32_t*)&h2; o.w = *(uint32_t*)&h3;
        ((uint4*)g_f16)[t] = o;
    } else {
        int e = (b - FEAT_BLOCKS) * blockDim.x + threadIdx.x;   // (tap, o, c)
        if (e >= 28 * 4096) return;
        int k = e >> 12, rem = e & 4095;
        int o = rem >> 6, c = rem & 63;
        float w = (k < 27) ? Wc[k * 4096 + c * 64 + o] : Wl[c * 64 + o];
        g_w16[e] = __float2half_rn(w);
    }
}

// ---------- main ----------
__global__ __launch_bounds__(NTHREADS, 2)
void conv_mma_kernel(const int* __restrict__ nb, const float* __restrict__ bc,
                     const float* __restrict__ bl, const float* __restrict__ gamma,
                     const float* __restrict__ beta, float* __restrict__ out)
{
    extern __shared__ __align__(16) char smem[];
    const uint32_t sb = smem_u32(smem);
    const int tid  = threadIdx.x;
    const int lane = tid & 31;
    const int w    = tid >> 5;       // 0..7
    const int group = lane >> 2;     // 0..7
    const int qp    = lane & 3;      // 0..3
    const int gvox = blockIdx.x * TILE_M + tid;
    const bool active = gvox < N_VOX;
    const int* nrow = nb + (long)gvox * NK;

    float c[2][8][4];
    #pragma unroll
    for (int mi = 0; mi < 2; mi++)
        #pragma unroll
        for (int nt = 0; nt < 8; nt++)
            #pragma unroll
            for (int r = 0; r < 4; r++) c[mi][nt][r] = 0.0f;

    // ---- issue helpers ----
    auto issueA = [&](int s, int k) {
        uint32_t dst = sb + s * STAGE + tid * ROWB;
        int idx = active ? nrow[k] : -1;
        if (idx >= 0) {
            const char* src = (const char*)(g_f16 + (size_t)idx * 64);
            #pragma unroll
            for (int j = 0; j < 8; j++) cpa16(dst + j * 16, src + j * 16);
        } else {
            float4 z = make_float4(0.f, 0.f, 0.f, 0.f);
            #pragma unroll
            for (int j = 0; j < 8; j++)
                *(float4*)(smem + s * STAGE + tid * ROWB + j * 16) = z;
        }
    };
    auto issueW = [&](uint32_t wbase, int k) {
        const char* srcb = (const char*)(g_w16 + (size_t)k * 4096);
        #pragma unroll
        for (int t = 0; t < 2; t++) {
            int ch = tid + t * NTHREADS;     // 512 chunks of 16B
            int row = ch >> 3, j = ch & 7;
            cpa16(wbase + row * ROWB + j * 16, srcb + ch * 16);
        }
    };

    // Software-pipelined tap GEMM: A frags double-buffered across k4,
    // B frags single-buffered across nt -> every LDS has MMA work behind it.
    auto do_tap = [&](uint32_t Ab, uint32_t Wb) {
        const uint32_t arow0 = Ab + (w * 32 + group) * ROWB + qp * 4;
        const uint32_t brow  = Wb + group * ROWB + qp * 4;
        uint32_t a_cur[2][4], a_nxt[2][4];
        // k4 = 0 A fragments
        #pragma unroll
        for (int mi = 0; mi < 2; mi++) {
            uint32_t base = arow0 + mi * 16 * ROWB;
            a_cur[mi][0] = lds32(base);
            a_cur[mi][1] = lds32(base + 8 * ROWB);
            a_cur[mi][2] = lds32(base + 16);
            a_cur[mi][3] = lds32(base + 8 * ROWB + 16);
        }
        #pragma unroll
        for (int k4 = 0; k4 < 4; k4++) {
            const int koff = k4 * 32;              // bytes: k4*16 halves
            // prefetch next k4's A fragments (hidden behind this k4's 16 MMAs)
            if (k4 < 3) {
                #pragma unroll
                for (int mi = 0; mi < 2; mi++) {
                    uint32_t base = arow0 + mi * 16 * ROWB + koff + 32;
                    a_nxt[mi][0] = lds32(base);
                    a_nxt[mi][1] = lds32(base + 8 * ROWB);
                    a_nxt[mi][2] = lds32(base + 16);
                    a_nxt[mi][3] = lds32(base + 8 * ROWB + 16);
                }
            }
            // B pipeline across nt
            uint32_t bn0 = lds32(brow + koff);
            uint32_t bn1 = lds32(brow + koff + 16);
            #pragma unroll
            for (int nt = 0; nt < 8; nt++) {
                uint32_t b0 = bn0, b1 = bn1;
                if (nt < 7) {
                    uint32_t baddr = brow + (nt + 1) * 8 * ROWB + koff;
                    bn0 = lds32(baddr);
                    bn1 = lds32(baddr + 16);
                }
                mma16816(c[0][nt], a_cur[0], b0, b1);
                mma16816(c[1][nt], a_cur[1], b0, b1);
            }
            if (k4 < 3) {
                #pragma unroll
                for (int mi = 0; mi < 2; mi++)
                    #pragma unroll
                    for (int r = 0; r < 4; r++) a_cur[mi][r] = a_nxt[mi][r];
            }
        }
    };

    // ---- prologue: taps 0,1 ----
    issueA(0, 0); issueW(sb + 0 * STAGE + A_BYTES, 0); CP_COMMIT();
    issueA(1, 1); issueW(sb + 1 * STAGE + A_BYTES, 1); CP_COMMIT();

    // ---- conv mainloop ----
    #pragma unroll 1
    for (int k = 0; k < NK; k++) {
        const int s = k & 1;
        if (k < NK - 1) CP_WAIT(1); else CP_WAIT(0);
        __syncthreads();
        do_tap(sb + s * STAGE, sb + s * STAGE + A_BYTES);
        __syncthreads();
        if (k + 2 < NK) {
            issueA(s, k + 2);
            issueW(sb + s * STAGE + A_BYTES, k + 2);
            CP_COMMIT();
        }
    }

    // ---- epilogue: +bc, convert to fp16 X in stage0 A; load W_lin ----
    issueW(sb + A_BYTES, 27); CP_COMMIT();
    #pragma unroll
    for (int nt = 0; nt < 8; nt++) {
        const int col0 = nt * 8 + qp * 2;
        const float b0 = bc[col0], b1 = bc[col0 + 1];
        #pragma unroll
        for (int mi = 0; mi < 2; mi++) {
            float x0 = c[mi][nt][0] + b0;
            float x1 = c[mi][nt][1] + b1;
            float x2 = c[mi][nt][2] + b0;
            float x3 = c[mi][nt][3] + b1;
            __half2 p0 = __floats2half2_rn(x0, x1);
            __half2 p1 = __floats2half2_rn(x2, x3);
            const int r0 = w * 32 + mi * 16 + group;
            sts32(sb + r0 * ROWB + col0 * 2, *(uint32_t*)&p0);
            sts32(sb + (r0 + 8) * ROWB + col0 * 2, *(uint32_t*)&p1);
        }
    }
    CP_WAIT(0);
    __syncthreads();

    // ---- linear GEMM (tap 27) ----
    #pragma unroll
    for (int mi = 0; mi < 2; mi++)
        #pragma unroll
        for (int nt = 0; nt < 8; nt++)
            #pragma unroll
            for (int r = 0; r < 4; r++) c[mi][nt][r] = 0.0f;
    do_tap(sb, sb + A_BYTES);

    // ---- +bl, layernorm in registers ----
    float sum[2][2] = {{0.f, 0.f}, {0.f, 0.f}};
    float sq [2][2] = {{0.f, 0.f}, {0.f, 0.f}};
    #pragma unroll
    for (int nt = 0; nt < 8; nt++) {
        const int col0 = nt * 8 + qp * 2;
        const float b0 = bl[col0], b1 = bl[col0 + 1];
        #pragma unroll
        for (int mi = 0; mi < 2; mi++) {
            float y0 = c[mi][nt][0] + b0, y1 = c[mi][nt][1] + b1;
            float y2 = c[mi][nt][2] + b0, y3 = c[mi][nt][3] + b1;
            c[mi][nt][0] = y0; c[mi][nt][1] = y1;
            c[mi][nt][2] = y2; c[mi][nt][3] = y3;
            sum[mi][0] += y0 + y1;            sq[mi][0] += y0 * y0 + y1 * y1;
            sum[mi][1] += y2 + y3;            sq[mi][1] += y2 * y2 + y3 * y3;
        }
    }
    #pragma unroll
    for (int off = 1; off <= 2; off <<= 1) {
        #pragma unroll
        for (int mi = 0; mi < 2; mi++)
            #pragma unroll
            for (int h = 0; h < 2; h++) {
                sum[mi][h] += __shfl_xor_sync(0xffffffffu, sum[mi][h], off);
                sq [mi][h] += __shfl_xor_sync(0xffffffffu, sq [mi][h], off);
            }
    }
    float mu[2][2], rs[2][2];
    #pragma unroll
    for (int mi = 0; mi < 2; mi++)
        #pragma unroll
        for (int h = 0; h < 2; h++) {
            float m = sum[mi][h] * (1.0f / 64.0f);
            float v = sq[mi][h] * (1.0f / 64.0f) - m * m;
            mu[mi][h] = m;
            rs[mi][h] = rsqrtf(v + LN_EPS);
        }
    const int base_row = blockIdx.x * TILE_M + w * 32 + group;
    #pragma unroll
    for (int nt = 0; nt < 8; nt++) {
        const int col0 = nt * 8 + qp * 2;
        const float g0 = gamma[col0], g1 = gamma[col0 + 1];
        const float be0 = beta[col0], be1 = beta[col0 + 1];
        #pragma unroll
        for (int mi = 0; mi < 2; mi++) {
            int r0 = base_row + mi * 16;
            int r1 = r0 + 8;
            if (r0 < N_VOX) {
                float2 o;
                o.x = g0 * (c[mi][nt][0] - mu[mi][0]) * rs[mi][0] + be0;
                o.y = g1 * (c[mi][nt][1] - mu[mi][0]) * rs[mi][0] + be1;
                *(float2*)(out + (size_t)r0 * 64 + col0) = o;
            }
            if (r1 < N_VOX) {
                float2 o;
                o.x = g0 * (c[mi][nt][2] - mu[mi][1]) * rs[mi][1] + be0;
                o.y = g1 * (c[mi][nt][3] - mu[mi][1]) * rs[mi][1] + be1;
                *(float2*)(out + (size_t)r1 * 64 + col0) = o;
            }
        }
    }
}

// ---------- launch ----------
extern "C" void kernel_launch(void* const* d_in, const int* in_sizes, int n_in,
                              void* d_out, int out_size)
{
    const float* feats = (const float*)d_in[0];
    const int*   nb    = (const int*)d_in[1];
    const float* Wc    = (const float*)d_in[2];
    const float* bc    = (const float*)d_in[3];
    const float* Wl    = (const float*)d_in[4];
    const float* bl    = (const float*)d_in[5];
    const float* gamma = (const float*)d_in[6];
    const float* beta  = (const float*)d_in[7];
    float* out = (float*)d_out;

    static int init = 0;
    if (!init) {
        cudaFuncSetAttribute(conv_mma_kernel,
                             cudaFuncAttributeMaxDynamicSharedMemorySize, SMEM_BYTES);
        init = 1;
    }
    prep_all<<<FEAT_BLOCKS + W_BLOCKS, 256>>>(feats, Wc, Wl);
    conv_mma_kernel<<<GRID_M, NTHREADS, SMEM_BYTES>>>(nb, bc, bl, gamma, beta, out);
}